// round 16
// baseline (speedup 1.0000x reference)
#include <cuda_runtime.h>
#include <cuda_bf16.h>
#include <cstdint>
#include <cstddef>

#define BB 8
#define CC 512
#define NN 2304
#define MD 128
#define NTILE 18    // NN / 128

typedef __nv_bfloat16 bf16;

// ---- scratch --------------------------------------------------------------
static __device__ bf16  d_Ehi1[(size_t)BB * NN * NN], d_Elo1[(size_t)BB * NN * NN];
static __device__ bf16  d_Ehi2[(size_t)BB * NN * NN], d_Elo2[(size_t)BB * NN * NN];
static __device__ float d_ps1 [(size_t)BB * NTILE * NN], d_ps2[(size_t)BB * NTILE * NN];
static __device__ float d_inv1[BB * NN], d_inv2[BB * NN];
static __device__ bf16  d_xhi [(size_t)BB * NN * CC], d_xlo [(size_t)BB * NN * CC];
static __device__ bf16  d_xvhi[(size_t)BB * NN * CC], d_xvlo[(size_t)BB * NN * CC];
static __device__ bf16  d_xhhi[(size_t)BB * NN * CC], d_xhlo[(size_t)BB * NN * CC];
static __device__ bf16  d_fahi[(size_t)BB * NN * MD], d_falo[(size_t)BB * NN * MD];
static __device__ bf16  d_fvhi[(size_t)BB * NN * MD], d_fvlo[(size_t)BB * NN * MD];
static __device__ bf16  d_fhhi[(size_t)BB * NN * MD], d_fhlo[(size_t)BB * NN * MD];
static __device__ bf16  d_Wahi [MD * CC], d_Walo [MD * CC];
static __device__ bf16  d_Wvhi [MD * CC], d_Wvlo [MD * CC];
static __device__ bf16  d_Wgavhi[MD * CC], d_Wgavlo[MD * CC];
static __device__ bf16  d_Wgahhi[MD * CC], d_Wgahlo[MD * CC];
static __device__ bf16  d_Wfavhi[CC * MD], d_Wfavlo[CC * MD];
static __device__ bf16  d_Wfahhi[CC * MD], d_Wfahlo[CC * MD];
static __device__ float d_gav [(size_t)BB * MD * NN];
static __device__ float d_gah [(size_t)BB * MD * NN];
static __device__ bf16  d_ghi1[(size_t)BB * MD * NN], d_glo1[(size_t)BB * MD * NN];
static __device__ bf16  d_ghi2[(size_t)BB * MD * NN], d_glo2[(size_t)BB * MD * NN];
static __device__ bf16  d_Om1hi[(size_t)BB * NN * MD], d_Om1lo[(size_t)BB * NN * MD];
static __device__ bf16  d_Om2hi[(size_t)BB * NN * MD], d_Om2lo[(size_t)BB * NN * MD];

// ---- host-side streams/events (created once at program init) --------------
static cudaStream_t g_s1 = 0;
static cudaEvent_t  g_evFork = 0, g_evGAV = 0, g_evFA = 0, g_evFH = 0, g_evEnd = 0;
namespace {
struct HXInit {
    HXInit() {
        cudaStreamCreateWithFlags(&g_s1, cudaStreamNonBlocking);
        cudaEventCreateWithFlags(&g_evFork, cudaEventDisableTiming);
        cudaEventCreateWithFlags(&g_evGAV,  cudaEventDisableTiming);
        cudaEventCreateWithFlags(&g_evFA,   cudaEventDisableTiming);
        cudaEventCreateWithFlags(&g_evFH,   cudaEventDisableTiming);
        cudaEventCreateWithFlags(&g_evEnd,  cudaEventDisableTiming);
    }
} g_hx_init;
}

__device__ __forceinline__ uint32_t smem_u32(const void* p) {
    uint32_t a;
    asm("{ .reg .u64 t; cvta.to.shared.u64 t, %1; cvt.u32.u64 %0, t; }" : "=r"(a) : "l"(p));
    return a;
}

// 32-k interleaved hi|lo tile: 128 rows x 128B; bytes [0,64)=hi, [64,128)=lo
__device__ __forceinline__ void tile_ld32(uint32_t sdst, const bf16* __restrict__ hi,
                                          const bf16* __restrict__ lo, int ld, int tid) {
#pragma unroll
    for (int it = 0; it < 2; ++it) {
        int s = tid + it * 256;
        int r = s >> 2, q = s & 3;
        uint32_t o = (uint32_t)(r * 128 + q * 16);
        uint32_t o1 = o ^ ((o >> 3) & 0x70);
        uint32_t o2 = (o + 64) ^ (((o + 64) >> 3) & 0x70);
        asm volatile("cp.async.cg.shared.global [%0], [%1], 16;"
                     :: "r"(sdst + o1), "l"(hi + (size_t)r * ld + q * 8) : "memory");
        asm volatile("cp.async.cg.shared.global [%0], [%1], 16;"
                     :: "r"(sdst + o2), "l"(lo + (size_t)r * ld + q * 8) : "memory");
    }
}

#define LDSM4(d, a)                                                          \
    asm volatile("ldmatrix.sync.aligned.m8n8.x4.shared.b16 {%0,%1,%2,%3}, [%4];" \
        : "=r"((d)[0]), "=r"((d)[1]), "=r"((d)[2]), "=r"((d)[3]) : "r"(a))
#define MMA(ac, af, b0, b1)                                                  \
    asm volatile("mma.sync.aligned.m16n8k16.row.col.f32.bf16.bf16.f32 "      \
        "{%0,%1,%2,%3}, {%4,%5,%6,%7}, {%8,%9}, {%0,%1,%2,%3};"              \
        : "+f"((ac)[0]), "+f"((ac)[1]), "+f"((ac)[2]), "+f"((ac)[3])         \
        : "r"((af)[0]), "r"((af)[1]), "r"((af)[2]), "r"((af)[3]),            \
          "r"(b0), "r"(b1))

// Shared 3-term mainloop macro body: processes nC chunks of 32 real-k.
// Expects: sb, tid, lane, li8, sel, mW, nW, acc declared; Ahi/Alo/ldA,
// Bhi/Blo/ldB pointers pre-offset to tile origin.
#define MAINLOOP3(Ahi, Alo, ldA, Bhi, Blo, ldB, nC)                           \
    tile_ld32(sb + 0,     Ahi, Alo, ldA, tid);                                \
    tile_ld32(sb + 16384, Bhi, Blo, ldB, tid);                                \
    asm volatile("cp.async.commit_group;" ::: "memory");                      \
    {                                                                         \
        int buf = 0;                                                          \
        for (int c = 0; c < (nC); ++c) {                                      \
            if (c + 1 < (nC)) {                                               \
                const uint32_t nb = sb + (buf ^ 1) * 32768;                   \
                tile_ld32(nb + 0,     (Ahi) + (size_t)(c + 1) * 32,           \
                          (Alo) + (size_t)(c + 1) * 32, ldA, tid);            \
                tile_ld32(nb + 16384, (Bhi) + (size_t)(c + 1) * 32,           \
                          (Blo) + (size_t)(c + 1) * 32, ldB, tid);            \
                asm volatile("cp.async.commit_group;" ::: "memory");          \
                asm volatile("cp.async.wait_group 1;" ::: "memory");          \
            } else {                                                          \
                asm volatile("cp.async.wait_group 0;" ::: "memory");          \
            }                                                                 \
            __syncthreads();                                                  \
            const uint32_t cb = sb + buf * 32768;                             \
            _Pragma("unroll")                                                 \
            for (int ks = 0; ks < 2; ++ks) {                                  \
                const int kb = ks * 32;                                       \
                uint32_t ah[4][4], al[4][4], bh[2][4], bl[2][4];              \
                _Pragma("unroll")                                             \
                for (int mi = 0; mi < 4; ++mi) {                              \
                    int row = mW + mi * 16 + li8 + (sel & 1) * 8;             \
                    uint32_t o  = (uint32_t)(row * 128 + kb + (sel >> 1) * 16); \
                    uint32_t oh = o ^ ((o >> 3) & 0x70);                      \
                    uint32_t ol = (o + 64) ^ (((o + 64) >> 3) & 0x70);        \
                    LDSM4(ah[mi], cb + oh);                                   \
                    LDSM4(al[mi], cb + ol);                                   \
                }                                                             \
                _Pragma("unroll")                                             \
                for (int nq = 0; nq < 2; ++nq) {                              \
                    int row = nW + nq * 16 + li8 + (sel >> 1) * 8;            \
                    uint32_t o  = (uint32_t)(row * 128 + kb + (sel & 1) * 16); \
                    uint32_t oh = o ^ ((o >> 3) & 0x70);                      \
                    uint32_t ol = (o + 64) ^ (((o + 64) >> 3) & 0x70);        \
                    LDSM4(bh[nq], cb + 16384 + oh);                           \
                    LDSM4(bl[nq], cb + 16384 + ol);                           \
                }                                                             \
                _Pragma("unroll")                                             \
                for (int mi = 0; mi < 4; ++mi)                                \
                    _Pragma("unroll")                                         \
                    for (int ni = 0; ni < 4; ++ni) {                          \
                        const int q = ni >> 1, p = (ni & 1) * 2;              \
                        MMA(acc[mi][ni], ah[mi], bh[q][p], bh[q][p + 1]);     \
                        MMA(acc[mi][ni], ah[mi], bl[q][p], bl[q][p + 1]);     \
                        MMA(acc[mi][ni], al[mi], bh[q][p], bh[q][p + 1]);     \
                    }                                                         \
            }                                                                 \
            __syncthreads();                                                  \
            buf ^= 1;                                                         \
        }                                                                     \
    }

// ---------------------------------------------------------------------------
// Generic 3-term GEMM: acc[m,n] = A[m,:].B[n,:], A/B explicit hi/lo, real K.
// EPI 0: BN-ReLU -> fhi/flo [n, MD]
// EPI 1: +bias -> fp32 Cf [m, NN]
// EPI 2: +bias + resid -> fp32 Cf [m, NN]
// ---------------------------------------------------------------------------
template<int EPI>
__global__ void __launch_bounds__(256, 2)
hmma3_mm(const bf16* __restrict__ Ahi, const bf16* __restrict__ Alo,
         size_t sA, int ldA,
         const bf16* __restrict__ Bhi, const bf16* __restrict__ Blo,
         size_t sB, int ldB, int K,
         float* __restrict__ Cf, size_t sC,
         bf16* __restrict__ O1, bf16* __restrict__ O2, size_t sO,
         const float* __restrict__ bias,
         const float* __restrict__ gam, const float* __restrict__ bet,
         const float* __restrict__ resid, size_t sR)
{
    extern __shared__ char smem[];
    const uint32_t sb = smem_u32(smem);
    const int tid = threadIdx.x, wid = tid >> 5, lane = tid & 31;
    const int b = blockIdx.z;
    const int m0 = blockIdx.y * 128, n0 = blockIdx.x * 128;
    Ahi += (size_t)b * sA + (size_t)m0 * ldA;
    Alo += (size_t)b * sA + (size_t)m0 * ldA;
    Bhi += (size_t)b * sB + (size_t)n0 * ldB;
    Blo += (size_t)b * sB + (size_t)n0 * ldB;
    if (EPI == 0) { O1 += (size_t)b * sO; O2 += (size_t)b * sO; }
    else          { Cf += (size_t)b * sC; if (EPI == 2) resid += (size_t)b * sR; }

    const int mW = (wid & 1) * 64, nW = (wid >> 1) * 32;
    const int li8 = lane & 7, sel = lane >> 3;
    float acc[4][4][4];
#pragma unroll
    for (int i = 0; i < 4; ++i)
#pragma unroll
        for (int j = 0; j < 4; ++j)
#pragma unroll
            for (int k = 0; k < 4; ++k) acc[i][j][k] = 0.f;

    const int nC = K >> 5;
    MAINLOOP3(Ahi, Alo, ldA, Bhi, Blo, ldB, nC)

    const int g8 = lane >> 2, tg = lane & 3;
    if (EPI == 0) {
        float (*stage)[129] = (float(*)[129])smem;
        const float rs = rsqrtf(1.f + 1e-5f);
#pragma unroll
        for (int mi = 0; mi < 4; ++mi) {
            const int r0 = mW + mi * 16 + g8, r1 = r0 + 8;
            const float s0 = gam[r0] * rs, b0 = fmaf(bias[r0], s0, bet[r0]);
            const float s1 = gam[r1] * rs, b1 = fmaf(bias[r1], s1, bet[r1]);
#pragma unroll
            for (int ni = 0; ni < 4; ++ni) {
                const int c = nW + ni * 8 + tg * 2;
                stage[c][r0]     = fmaxf(fmaf(acc[mi][ni][0], s0, b0), 0.f);
                stage[c + 1][r0] = fmaxf(fmaf(acc[mi][ni][1], s0, b0), 0.f);
                stage[c][r1]     = fmaxf(fmaf(acc[mi][ni][2], s1, b1), 0.f);
                stage[c + 1][r1] = fmaxf(fmaf(acc[mi][ni][3], s1, b1), 0.f);
            }
        }
        __syncthreads();
        for (int e = tid; e < 16384; e += 256) {
            int nn = e >> 7, m = e & 127;
            float v = stage[nn][m];
            bf16 h = __float2bfloat16(v);
            size_t o = (size_t)(n0 + nn) * MD + m;
            O1[o] = h;
            O2[o] = __float2bfloat16(v - __bfloat162float(h));
        }
    } else {
#pragma unroll
        for (int mi = 0; mi < 4; ++mi) {
            const int r0 = m0 + mW + mi * 16 + g8;
            const float bs0 = bias[r0], bs1 = bias[r0 + 8];
#pragma unroll
            for (int ni = 0; ni < 4; ++ni) {
                const int n = n0 + nW + ni * 8 + tg * 2;
                const size_t i0r = (size_t)r0 * NN + n, i1r = (size_t)(r0 + 8) * NN + n;
                float a0 = acc[mi][ni][0] + bs0, a1 = acc[mi][ni][1] + bs0;
                float a2 = acc[mi][ni][2] + bs1, a3 = acc[mi][ni][3] + bs1;
                if (EPI == 2) {
                    float2 rs0 = *(const float2*)&resid[i0r];
                    float2 rs1 = *(const float2*)&resid[i1r];
                    a0 += rs0.x; a1 += rs0.y; a2 += rs1.x; a3 += rs1.y;
                }
                *(float2*)&Cf[i0r] = make_float2(a0, a1);
                *(float2*)&Cf[i1r] = make_float2(a2, a3);
            }
        }
    }
}

// ---------------------------------------------------------------------------
// Score: E[j,n] = exp(alpha * <fa[j,:], fq[n,:]>), explicit hi/lo, K=MD.
// Writes Ehi/Elo + per-tile column partial sums PS.
// ---------------------------------------------------------------------------
__global__ void __launch_bounds__(256, 2)
hmma3_score(const bf16* __restrict__ Ahi, const bf16* __restrict__ Alo,
            const bf16* __restrict__ Bhi, const bf16* __restrict__ Blo,
            size_t sF,
            bf16* __restrict__ Ehi, bf16* __restrict__ Elo,
            float* __restrict__ PS, float alpha)
{
    extern __shared__ char smem[];
    const uint32_t sb = smem_u32(smem);
    const int tid = threadIdx.x, wid = tid >> 5, lane = tid & 31;
    const int b = blockIdx.z;
    const int i0 = blockIdx.y * 128, j0 = blockIdx.x * 128;
    Ahi += (size_t)b * sF + (size_t)i0 * MD;
    Alo += (size_t)b * sF + (size_t)i0 * MD;
    Bhi += (size_t)b * sF + (size_t)j0 * MD;
    Blo += (size_t)b * sF + (size_t)j0 * MD;
    Ehi += (size_t)b * NN * NN;
    Elo += (size_t)b * NN * NN;

    const int mW = (wid & 1) * 64, nW = (wid >> 1) * 32;
    const int li8 = lane & 7, sel = lane >> 3;
    float acc[4][4][4];
#pragma unroll
    for (int i = 0; i < 4; ++i)
#pragma unroll
        for (int j = 0; j < 4; ++j)
#pragma unroll
            for (int k = 0; k < 4; ++k) acc[i][j][k] = 0.f;

    MAINLOOP3(Ahi, Alo, MD, Bhi, Blo, MD, 4)

    const int g8 = lane >> 2, tg = lane & 3;
    float ev[4][4][4];
#pragma unroll
    for (int mi = 0; mi < 4; ++mi)
#pragma unroll
        for (int ni = 0; ni < 4; ++ni)
#pragma unroll
            for (int k = 0; k < 4; ++k)
                ev[mi][ni][k] = __expf(acc[mi][ni][k] * alpha);
#pragma unroll
    for (int mi = 0; mi < 4; ++mi)
#pragma unroll
        for (int ni = 0; ni < 4; ++ni) {
            const int r  = i0 + mW + mi * 16 + g8;
            const int cN = j0 + nW + ni * 8 + tg * 2;
            __nv_bfloat162 h01 = __floats2bfloat162_rn(ev[mi][ni][0], ev[mi][ni][1]);
            __nv_bfloat162 h23 = __floats2bfloat162_rn(ev[mi][ni][2], ev[mi][ni][3]);
            float2 f01 = __bfloat1622float2(h01);
            float2 f23 = __bfloat1622float2(h23);
            __nv_bfloat162 l01 = __floats2bfloat162_rn(ev[mi][ni][0] - f01.x,
                                                       ev[mi][ni][1] - f01.y);
            __nv_bfloat162 l23 = __floats2bfloat162_rn(ev[mi][ni][2] - f23.x,
                                                       ev[mi][ni][3] - f23.y);
            *(__nv_bfloat162*)&Ehi[(size_t)r * NN + cN]       = h01;
            *(__nv_bfloat162*)&Elo[(size_t)r * NN + cN]       = l01;
            *(__nv_bfloat162*)&Ehi[(size_t)(r + 8) * NN + cN] = h23;
            *(__nv_bfloat162*)&Elo[(size_t)(r + 8) * NN + cN] = l23;
        }
    float cs[8];
#pragma unroll
    for (int ni = 0; ni < 4; ++ni)
#pragma unroll
        for (int par = 0; par < 2; ++par) {
            float s = 0.f;
#pragma unroll
            for (int mi = 0; mi < 4; ++mi)
                s += ev[mi][ni][par] + ev[mi][ni][2 + par];
            cs[ni * 2 + par] = s;
        }
#pragma unroll
    for (int o = 4; o <= 16; o <<= 1)
#pragma unroll
        for (int e = 0; e < 8; ++e)
            cs[e] += __shfl_xor_sync(0xffffffffu, cs[e], o);
    float* sP = (float*)smem;
    if (g8 == 0) {
#pragma unroll
        for (int ni = 0; ni < 4; ++ni)
#pragma unroll
            for (int par = 0; par < 2; ++par)
                sP[(wid & 1) * 128 + nW + ni * 8 + tg * 2 + par] = cs[ni * 2 + par];
    }
    __syncthreads();
    if (tid < 128)
        PS[((size_t)(b * NTILE + blockIdx.y)) * NN + j0 + tid] = sP[tid] + sP[128 + tid];
}

// inv[b][n] = 1 / sum_t PS[b][t][n]
__global__ void __launch_bounds__(256)
finalize_inv(const float* __restrict__ PS, float* __restrict__ inv)
{
    const int b = blockIdx.z;
    const int n = blockIdx.x * 256 + threadIdx.x;
    float s = 0.f;
#pragma unroll
    for (int t = 0; t < NTILE; ++t)
        s += PS[((size_t)(b * NTILE + t)) * NN + n];
    inv[b * NN + n] = 1.f / s;
}

// ghi/glo = split(g * inv[n])
__global__ void __launch_bounds__(256)
gscale(const float* __restrict__ g, const float* __restrict__ inv,
       bf16* __restrict__ Ghi, bf16* __restrict__ Glo)
{
    const int b = blockIdx.z;
    const size_t i2 = ((size_t)blockIdx.x * 256 + threadIdx.x) * 2;
    const size_t base = (size_t)b * MD * NN;
    const int n = (int)(i2 % NN);
    float2 v = *(const float2*)&g[base + i2];
    float2 iv = *(const float2*)&inv[b * NN + n];
    v.x *= iv.x; v.y *= iv.y;
    __nv_bfloat162 h = __floats2bfloat162_rn(v.x, v.y);
    float2 f = __bfloat1622float2(h);
    __nv_bfloat162 l = __floats2bfloat162_rn(v.x - f.x, v.y - f.y);
    *(__nv_bfloat162*)&Ghi[base + i2] = h;
    *(__nv_bfloat162*)&Glo[base + i2] = l;
}

// ---------------------------------------------------------------------------
// Apply: om[m,j] = sum_n g'[m,n]*E[j,n]; 3-term, K=NN. Emits Om hi/lo [j, MD].
// ---------------------------------------------------------------------------
__global__ void __launch_bounds__(256, 2)
apply_fused(const bf16* __restrict__ Ghi, const bf16* __restrict__ Glo,
            const bf16* __restrict__ Ehi, const bf16* __restrict__ Elo,
            bf16* __restrict__ O1, bf16* __restrict__ O2)
{
    extern __shared__ char smem[];
    const uint32_t sb = smem_u32(smem);
    const int tid = threadIdx.x, wid = tid >> 5, lane = tid & 31;
    const int b = blockIdx.z;
    const int j0 = blockIdx.x * 128;
    Ghi += (size_t)b * MD * NN;
    Glo += (size_t)b * MD * NN;
    Ehi += (size_t)b * NN * NN + (size_t)j0 * NN;
    Elo += (size_t)b * NN * NN + (size_t)j0 * NN;
    O1  += (size_t)b * NN * MD;
    O2  += (size_t)b * NN * MD;

    const int mW = (wid & 1) * 64, nW = (wid >> 1) * 32;
    const int li8 = lane & 7, sel = lane >> 3;
    float acc[4][4][4];
#pragma unroll
    for (int i = 0; i < 4; ++i)
#pragma unroll
        for (int j = 0; j < 4; ++j)
#pragma unroll
            for (int k = 0; k < 4; ++k) acc[i][j][k] = 0.f;

    MAINLOOP3(Ghi, Glo, NN, Ehi, Elo, NN, 72)

    float (*stage)[129] = (float(*)[129])smem;
    const int g8 = lane >> 2, tg = lane & 3;
#pragma unroll
    for (int mi = 0; mi < 4; ++mi) {
        const int r0 = mW + mi * 16 + g8;
#pragma unroll
        for (int ni = 0; ni < 4; ++ni) {
            const int c = nW + ni * 8 + tg * 2;
            stage[c][r0]         = acc[mi][ni][0];
            stage[c + 1][r0]     = acc[mi][ni][1];
            stage[c][r0 + 8]     = acc[mi][ni][2];
            stage[c + 1][r0 + 8] = acc[mi][ni][3];
        }
    }
    __syncthreads();
    for (int e = tid; e < 16384; e += 256) {
        int jl = e >> 7, m = e & 127;
        float v = stage[jl][m];
        bf16 h = __float2bfloat16(v);
        size_t o = (size_t)(j0 + jl) * MD + m;
        O1[o] = h;
        O2[o] = __float2bfloat16(v - __bfloat162float(h));
    }
}

// ---------------------------------------------------------------------------
// x split-transpose: X fp32 [C,N] per batch -> Xhi/Xlo bf16 [N, C]
// ---------------------------------------------------------------------------
__global__ void __launch_bounds__(256)
xsplitT(const float* __restrict__ X, bf16* __restrict__ Xhi, bf16* __restrict__ Xlo)
{
    extern __shared__ char smem[];
    float (*stage)[129] = (float(*)[129])smem;
    const int b = blockIdx.z;
    const int c0 = blockIdx.y * 128, n0 = blockIdx.x * 128;
    X   += (size_t)b * CC * NN;
    Xhi += (size_t)b * NN * CC;
    Xlo += (size_t)b * NN * CC;
    const int tid = threadIdx.x;

    for (int e = tid; e < 16384; e += 256) {
        int cc = e >> 7, nn = e & 127;
        stage[nn][cc] = X[(size_t)(c0 + cc) * NN + n0 + nn];
    }
    __syncthreads();
    for (int e = tid; e < 16384; e += 256) {
        int nn = e >> 7, cc = e & 127;
        float v = stage[nn][cc];
        bf16 h = __float2bfloat16(v);
        size_t o = (size_t)(n0 + nn) * CC + c0 + cc;
        Xhi[o] = h;
        Xlo[o] = __float2bfloat16(v - __bfloat162float(h));
    }
}

// weight split: W fp32 [M*K] -> hi/lo arrays
__global__ void __launch_bounds__(256)
wsplit(const float* __restrict__ W, bf16* __restrict__ Ohi, bf16* __restrict__ Olo)
{
    const int idx = blockIdx.x * 256 + threadIdx.x;
    float v = W[idx];
    bf16 h = __float2bfloat16(v);
    Ohi[idx] = h;
    Olo[idx] = __float2bfloat16(v - __bfloat162float(h));
}

// ---------------------------------------------------------------------------

extern "C" void kernel_launch(void* const* d_in, const int* in_sizes, int n_in,
                              void* d_out, int out_size)
{
    const float* x    = (const float*)d_in[0];
    const float* x_h  = (const float*)d_in[1];
    const float* x_v  = (const float*)d_in[2];
    const float* Wa   = (const float*)d_in[3];
    const float* ba   = (const float*)d_in[4];
    const float* ga   = (const float*)d_in[5];
    const float* ta   = (const float*)d_in[6];
    const float* Wv   = (const float*)d_in[7];
    const float* bv   = (const float*)d_in[8];
    const float* gv   = (const float*)d_in[9];
    const float* tv   = (const float*)d_in[10];
    const float* Wgav = (const float*)d_in[11];
    const float* bgav = (const float*)d_in[12];
    const float* Wgah = (const float*)d_in[13];
    const float* bgah = (const float*)d_in[14];
    const float* Wfav = (const float*)d_in[15];
    const float* bfav = (const float*)d_in[16];
    const float* Wfah = (const float*)d_in[17];
    const float* bfah = (const float*)d_in[18];
    float* out = (float*)d_out;

    float *ps1, *ps2, *inv1, *inv2, *gav, *gah;
    bf16 *Ehi1, *Elo1, *Ehi2, *Elo2;
    bf16 *xhi, *xlo, *xvhi, *xvlo, *xhhi, *xhlo;
    bf16 *fahi, *falo, *fvhi, *fvlo, *fhhi, *fhlo;
    bf16 *Wahi, *Walo, *Wvhi, *Wvlo, *Wgavhi, *Wgavlo, *Wgahhi, *Wgahlo;
    bf16 *Wfavhi, *Wfavlo, *Wfahhi, *Wfahlo;
    bf16 *ghi1, *glo1, *ghi2, *glo2, *Om1hi, *Om1lo, *Om2hi, *Om2lo;
    cudaGetSymbolAddress((void**)&Ehi1,   d_Ehi1);
    cudaGetSymbolAddress((void**)&Elo1,   d_Elo1);
    cudaGetSymbolAddress((void**)&Ehi2,   d_Ehi2);
    cudaGetSymbolAddress((void**)&Elo2,   d_Elo2);
    cudaGetSymbolAddress((void**)&ps1,    d_ps1);
    cudaGetSymbolAddress((void**)&ps2,    d_ps2);
    cudaGetSymbolAddress((void**)&inv1,   d_inv1);
    cudaGetSymbolAddress((void**)&inv2,   d_inv2);
    cudaGetSymbolAddress((void**)&xhi,    d_xhi);
    cudaGetSymbolAddress((void**)&xlo,    d_xlo);
    cudaGetSymbolAddress((void**)&xvhi,   d_xvhi);
    cudaGetSymbolAddress((void**)&xvlo,   d_xvlo);
    cudaGetSymbolAddress((void**)&xhhi,   d_xhhi);
    cudaGetSymbolAddress((void**)&xhlo,   d_xhlo);
    cudaGetSymbolAddress((void**)&fahi,   d_fahi);
    cudaGetSymbolAddress((void**)&falo,   d_falo);
    cudaGetSymbolAddress((void**)&fvhi,   d_fvhi);
    cudaGetSymbolAddress((void**)&fvlo,   d_fvlo);
    cudaGetSymbolAddress((void**)&fhhi,   d_fhhi);
    cudaGetSymbolAddress((void**)&fhlo,   d_fhlo);
    cudaGetSymbolAddress((void**)&Wahi,   d_Wahi);
    cudaGetSymbolAddress((void**)&Walo,   d_Walo);
    cudaGetSymbolAddress((void**)&Wvhi,   d_Wvhi);
    cudaGetSymbolAddress((void**)&Wvlo,   d_Wvlo);
    cudaGetSymbolAddress((void**)&Wgavhi, d_Wgavhi);
    cudaGetSymbolAddress((void**)&Wgavlo, d_Wgavlo);
    cudaGetSymbolAddress((void**)&Wgahhi, d_Wgahhi);
    cudaGetSymbolAddress((void**)&Wgahlo, d_Wgahlo);
    cudaGetSymbolAddress((void**)&Wfavhi, d_Wfavhi);
    cudaGetSymbolAddress((void**)&Wfavlo, d_Wfavlo);
    cudaGetSymbolAddress((void**)&Wfahhi, d_Wfahhi);
    cudaGetSymbolAddress((void**)&Wfahlo, d_Wfahlo);
    cudaGetSymbolAddress((void**)&gav,    d_gav);
    cudaGetSymbolAddress((void**)&gah,    d_gah);
    cudaGetSymbolAddress((void**)&ghi1,   d_ghi1);
    cudaGetSymbolAddress((void**)&glo1,   d_glo1);
    cudaGetSymbolAddress((void**)&ghi2,   d_ghi2);
    cudaGetSymbolAddress((void**)&glo2,   d_glo2);
    cudaGetSymbolAddress((void**)&Om1hi,  d_Om1hi);
    cudaGetSymbolAddress((void**)&Om1lo,  d_Om1lo);
    cudaGetSymbolAddress((void**)&Om2hi,  d_Om2hi);
    cudaGetSymbolAddress((void**)&Om2lo,  d_Om2lo);

    const int SMEM_MM = 66048;   // mainloop 64KB; EPI0/apply stage 66048
    const int SMEM_SC = 65536;
    const int SMEM_ST = 66048;
    cudaFuncSetAttribute(hmma3_mm<0>, cudaFuncAttributeMaxDynamicSharedMemorySize, SMEM_MM);
    cudaFuncSetAttribute(hmma3_mm<1>, cudaFuncAttributeMaxDynamicSharedMemorySize, SMEM_MM);
    cudaFuncSetAttribute(hmma3_mm<2>, cudaFuncAttributeMaxDynamicSharedMemorySize, SMEM_MM);
    cudaFuncSetAttribute(hmma3_score, cudaFuncAttributeMaxDynamicSharedMemorySize, SMEM_SC);
    cudaFuncSetAttribute(apply_fused, cudaFuncAttributeMaxDynamicSharedMemorySize, SMEM_MM);
    cudaFuncSetAttribute(xsplitT,     cudaFuncAttributeMaxDynamicSharedMemorySize, SMEM_ST);

    const size_t sXc = (size_t)NN * CC;   // x hi/lo per batch
    const size_t sFh = (size_t)NN * MD;   // f / Om hi/lo per batch
    const size_t sG  = (size_t)MD * NN;
    const size_t sX  = (size_t)CC * NN;
    const size_t halfOut = (size_t)BB * CC * NN;
    const float alpha = 0.08838834764831845f;  // 128^-0.5

    dim3 blk(256);
    dim3 gXT   (NN / 128, CC / 128, BB);
    dim3 gConv (NN / 128, 1, BB);
    dim3 gScore(NN / 128, NN / 128, BB);
    dim3 gApply(NN / 128, 1, BB);
    dim3 gOut  (NN / 128, CC / 128, BB);
    dim3 gInv  (NN / 256, 1, BB);
    dim3 gGs   ((MD * NN / 2) / 256, 1, BB);

    cudaStream_t s0 = 0, s1 = g_s1;

    // fork
    cudaEventRecord(g_evFork, s0);
    cudaStreamWaitEvent(s1, g_evFork, 0);

    // --- stream 0: x pack + faT/gah/gav convs ---
    xsplitT<<<gXT, blk, SMEM_ST, s0>>>(x, xhi, xlo);
    wsplit<<<(MD * CC) / 256, blk, 0, s0>>>(Wa,   Wahi,   Walo);
    wsplit<<<(MD * CC) / 256, blk, 0, s0>>>(Wgah, Wgahhi, Wgahlo);
    wsplit<<<(MD * CC) / 256, blk, 0, s0>>>(Wgav, Wgavhi, Wgavlo);
    wsplit<<<(CC * MD) / 256, blk, 0, s0>>>(Wfah, Wfahhi, Wfahlo);
    hmma3_mm<0><<<gConv, blk, SMEM_MM, s0>>>(Wahi, Walo, 0, CC, xhi, xlo, sXc, CC, CC,
                                             nullptr, 0, fahi, falo, sFh, ba, ga, ta, nullptr, 0);
    cudaEventRecord(g_evFA, s0);
    hmma3_mm<1><<<gConv, blk, SMEM_MM, s0>>>(Wgahhi, Wgahlo, 0, CC, xhi, xlo, sXc, CC, CC,
                                             gah, sG, nullptr, nullptr, 0, bgah, nullptr, nullptr, nullptr, 0);
    hmma3_mm<1><<<gConv, blk, SMEM_MM, s0>>>(Wgavhi, Wgavlo, 0, CC, xhi, xlo, sXc, CC, CC,
                                             gav, sG, nullptr, nullptr, 0, bgav, nullptr, nullptr, nullptr, 0);
    cudaEventRecord(g_evGAV, s0);

    // --- stream 1: x_h FIRST (fh on s0 critical path), then x_v ---
    xsplitT<<<gXT, blk, SMEM_ST, s1>>>(x_h, xhhi, xhlo);
    wsplit<<<(MD * CC) / 256, blk, 0, s1>>>(Wv, Wvhi, Wvlo);
    hmma3_mm<0><<<gConv, blk, SMEM_MM, s1>>>(Wvhi, Wvlo, 0, CC, xhhi, xhlo, sXc, CC, CC,
                                             nullptr, 0, fhhi, fhlo, sFh, bv, gv, tv, nullptr, 0);
    cudaEventRecord(g_evFH, s1);
    xsplitT<<<gXT, blk, SMEM_ST, s1>>>(x_v, xvhi, xvlo);
    hmma3_mm<0><<<gConv, blk, SMEM_MM, s1>>>(Wvhi, Wvlo, 0, CC, xvhi, xvlo, sXc, CC, CC,
                                             nullptr, 0, fvhi, fvlo, sFh, bv, gv, tv, nullptr, 0);
    wsplit<<<(CC * MD) / 256, blk, 0, s1>>>(Wfav, Wfavhi, Wfavlo);

    // --- stream 0: pass ah (needs fh from s1) ---
    cudaStreamWaitEvent(s0, g_evFH, 0);
    hmma3_score<<<gScore, blk, SMEM_SC, s0>>>(fahi, falo, fhhi, fhlo, sFh, Ehi1, Elo1, ps1, alpha);
    finalize_inv<<<gInv, blk, 0, s0>>>(ps1, inv1);
    gscale<<<gGs, blk, 0, s0>>>(gah, inv1, ghi1, glo1);
    apply_fused<<<gApply, blk, SMEM_MM, s0>>>(ghi1, glo1, Ehi1, Elo1, Om1hi, Om1lo);
    hmma3_mm<2><<<gOut, blk, SMEM_MM, s0>>>(Wfahhi, Wfahlo, 0, MD, Om1hi, Om1lo, sFh, MD, MD,
                                            out, sX, nullptr, nullptr, 0, bfah, nullptr, nullptr, x, sX);

    // --- stream 1: pass av (needs fa + gav from s0) ---
    cudaStreamWaitEvent(s1, g_evFA, 0);
    hmma3_score<<<gScore, blk, SMEM_SC, s1>>>(fahi, falo, fvhi, fvlo, sFh, Ehi2, Elo2, ps2, alpha);
    finalize_inv<<<gInv, blk, 0, s1>>>(ps2, inv2);
    cudaStreamWaitEvent(s1, g_evGAV, 0);
    gscale<<<gGs, blk, 0, s1>>>(gav, inv2, ghi2, glo2);
    apply_fused<<<gApply, blk, SMEM_MM, s1>>>(ghi2, glo2, Ehi2, Elo2, Om2hi, Om2lo);
    hmma3_mm<2><<<gOut, blk, SMEM_MM, s1>>>(Wfavhi, Wfavlo, 0, MD, Om2hi, Om2lo, sFh, MD, MD,
                                            out + halfOut, sX, nullptr, nullptr, 0, bfav, nullptr, nullptr, x, sX);

    // join
    cudaEventRecord(g_evEnd, s1);
    cudaStreamWaitEvent(s0, g_evEnd, 0);
}